// round 2
// baseline (speedup 1.0000x reference)
#include <cuda_runtime.h>
#include <cstdint>

// out[i,j,k] = sum_d x[i+1,d]*x[j+1,d]*Wp[d,k] + b[k]
// (diff_term is antisymmetric -> cancelled by symmetrization; prod_term already symmetric)

#define LSEQ 512
#define DDIM 1280
#define OUTN 510
#define TILE 64
#define BK   16
#define NT   8            // ceil(510/64)
#define NTRI 36           // 8*9/2 triangular tiles
#define SPLITS 4
#define KCHUNK (DDIM / SPLITS)   // 320

#define ZS_STRIDE 66      // in float2 (8B) units, padded for bank/align
#define XS_STRIDE 68      // in floats, padded

__device__ __forceinline__ unsigned long long pack2(float lo, float hi) {
    unsigned long long r;
    asm("mov.b64 %0, {%1, %2};" : "=l"(r) : "f"(lo), "f"(hi));
    return r;
}
__device__ __forceinline__ void unpack2(unsigned long long v, float& lo, float& hi) {
    asm("mov.b64 {%0, %1}, %2;" : "=f"(lo), "=f"(hi) : "l"(v));
}
__device__ __forceinline__ unsigned long long fma2(unsigned long long a,
                                                   unsigned long long b,
                                                   unsigned long long c) {
    unsigned long long d;
    asm("fma.rn.f32x2 %0, %1, %2, %3;" : "=l"(d) : "l"(a), "l"(b), "l"(c));
    return d;
}

__global__ void init_out_kernel(float* __restrict__ out, const float* __restrict__ b) {
    int n = blockIdx.x * blockDim.x + threadIdx.x;
    const int total = OUTN * OUTN * 2;
    if (n < total) out[n] = b[n & 1];
}

__global__ __launch_bounds__(256, 1)
void pcm_gram_kernel(const float* __restrict__ x,
                     const float* __restrict__ W,
                     float* __restrict__ out) {
    __shared__ unsigned long long Zs[BK * ZS_STRIDE]; // Zs[d][row_i] = (x*wp0, x*wp1)
    __shared__ float Xs[BK * XS_STRIDE];              // Xs[d][row_j] = x

    // triangular tile decode: blockIdx.x in [0, NTRI)
    int t = blockIdx.x;
    int ti = 0;
    while (t >= NT - ti) { t -= NT - ti; ++ti; }
    int tj = ti + t;
    int split = blockIdx.y;

    const int tid = threadIdx.x;
    const int tx = tid & 15;       // output col group
    const int ty = tid >> 4;       // output row group
    const int rowLd = tid >> 2;    // 0..63 (tile row for loads)
    const int segLd = tid & 3;     // 0..3  (which 4-wide d segment)

    const int iBase = ti * TILE;
    const int jBase = tj * TILE;
    const int dBase0 = split * KCHUNK;

    unsigned long long acc[4][4];
#pragma unroll
    for (int a = 0; a < 4; a++)
#pragma unroll
        for (int c = 0; c < 4; c++) acc[a][c] = 0ull;

    for (int dBase = dBase0; dBase < dBase0 + KCHUNK; dBase += BK) {
        const int d0 = dBase + segLd * 4;

        // ---- load Zs: rows of the i-tile, premultiplied by Wp[:,0/1] ----
        int gi = iBase + rowLd;
        float4 xv = make_float4(0.f, 0.f, 0.f, 0.f);
        if (gi < OUTN) xv = *(const float4*)&x[(size_t)(gi + 1) * DDIM + d0];
        // W row-major (2560,2): Wp[d][k] = W[2*d + k]
        float4 w01 = *(const float4*)&W[2 * d0];       // d0:(w0,w1)  d0+1:(w0,w1)
        float4 w23 = *(const float4*)&W[2 * d0 + 4];   // d0+2, d0+3

        Zs[(segLd * 4 + 0) * ZS_STRIDE + rowLd] = pack2(xv.x * w01.x, xv.x * w01.y);
        Zs[(segLd * 4 + 1) * ZS_STRIDE + rowLd] = pack2(xv.y * w01.z, xv.y * w01.w);
        Zs[(segLd * 4 + 2) * ZS_STRIDE + rowLd] = pack2(xv.z * w23.x, xv.z * w23.y);
        Zs[(segLd * 4 + 3) * ZS_STRIDE + rowLd] = pack2(xv.w * w23.z, xv.w * w23.w);

        // ---- load Xs: rows of the j-tile ----
        int gj = jBase + rowLd;
        float4 yv = make_float4(0.f, 0.f, 0.f, 0.f);
        if (gj < OUTN) yv = *(const float4*)&x[(size_t)(gj + 1) * DDIM + d0];
        Xs[(segLd * 4 + 0) * XS_STRIDE + rowLd] = yv.x;
        Xs[(segLd * 4 + 1) * XS_STRIDE + rowLd] = yv.y;
        Xs[(segLd * 4 + 2) * XS_STRIDE + rowLd] = yv.z;
        Xs[(segLd * 4 + 3) * XS_STRIDE + rowLd] = yv.w;

        __syncthreads();

#pragma unroll
        for (int kk = 0; kk < BK; kk++) {
            unsigned long long z[4];
            const unsigned long long* zrow = &Zs[kk * ZS_STRIDE + ty * 4];
#pragma unroll
            for (int a = 0; a < 4; a++) z[a] = zrow[a];

            float4 xf = *(const float4*)&Xs[kk * XS_STRIDE + tx * 4];
            unsigned long long xp[4];
            xp[0] = pack2(xf.x, xf.x);
            xp[1] = pack2(xf.y, xf.y);
            xp[2] = pack2(xf.z, xf.z);
            xp[3] = pack2(xf.w, xf.w);

#pragma unroll
            for (int a = 0; a < 4; a++)
#pragma unroll
                for (int c = 0; c < 4; c++)
                    acc[a][c] = fma2(z[a], xp[c], acc[a][c]);
        }
        __syncthreads();
    }

    // ---- epilogue: atomic accumulate (split-K), mirror for off-diagonal tiles ----
    const bool mirror = (ti != tj);
#pragma unroll
    for (int a = 0; a < 4; a++) {
        int i = iBase + ty * 4 + a;
        if (i >= OUTN) continue;
#pragma unroll
        for (int c = 0; c < 4; c++) {
            int j = jBase + tx * 4 + c;
            if (j >= OUTN) continue;
            float v0, v1;
            unpack2(acc[a][c], v0, v1);
            float* p = &out[((size_t)i * OUTN + j) * 2];
            atomicAdd(p + 0, v0);
            atomicAdd(p + 1, v1);
            if (mirror) {
                float* q = &out[((size_t)j * OUTN + i) * 2];
                atomicAdd(q + 0, v0);
                atomicAdd(q + 1, v1);
            }
        }
    }
}

extern "C" void kernel_launch(void* const* d_in, const int* in_sizes, int n_in,
                              void* d_out, int out_size) {
    const float* x = (const float*)d_in[0];   // (1,512,1280) fp32
    const float* W = (const float*)d_in[1];   // (2560,2) fp32
    const float* b = (const float*)d_in[2];   // (2,) fp32
    float* out = (float*)d_out;               // (1,510,510,2) fp32

    const int total = OUTN * OUTN * 2;
    init_out_kernel<<<(total + 255) / 256, 256>>>(out, b);

    dim3 grid(NTRI, SPLITS);
    pcm_gram_kernel<<<grid, 256>>>(x, W, out);
}

// round 4
// speedup vs baseline: 1.9499x; 1.9499x over previous
#include <cuda_runtime.h>
#include <cuda_bf16.h>
#include <cstdint>

// out[i,j,k] = sum_d x[i+1,d]*x[j+1,d]*Wp[d,k] + b[k]
// (diff_term antisymmetric -> cancels under (i,j) symmetrization; prod_term symmetric)
//
// bf16 hi/lo split (AhBh + AhBl + AlBh, err ~2^-16) on legacy mma.sync (HMMA,
// family-portable to sm_103 plain target). 136 triangular 32x32 tiles, K=1280.

#define OUTN 510
#define DDIM 1280
#define NTB 16            // 32-wide tiles per dim
#define NTRI 136          // 16*17/2
#define KC 64             // K elements per pipeline chunk
#define NCH 20            // 1280/64
#define STAGES 3
#define STAGE_BYTES 24576  // Ahi 8K | Alo 8K | Bhi 4K | Blo 4K
#define SA_HI 0
#define SA_LO 8192
#define SB_HI 16384
#define SB_LO 20480
#define SMEM_REQ (STAGES * STAGE_BYTES + 128)

__device__ __align__(128) __nv_bfloat16 g_Xhi[512 * DDIM];
__device__ __align__(128) __nv_bfloat16 g_Xlo[512 * DDIM];
__device__ __align__(128) __nv_bfloat16 g_Zhi[2][512 * DDIM];
__device__ __align__(128) __nv_bfloat16 g_Zlo[2][512 * DDIM];

// ---------------- helpers ----------------
__device__ __forceinline__ uint32_t smem_u32(const void* p) {
    uint32_t a;
    asm("{ .reg .u64 t; cvta.to.shared.u64 t, %1; cvt.u32.u64 %0, t; }" : "=r"(a) : "l"(p));
    return a;
}
__device__ __forceinline__ uint32_t pkbf2(float a, float b) {
    __nv_bfloat162 t = __floats2bfloat162_rn(a, b);
    return *reinterpret_cast<uint32_t*>(&t);
}
__device__ __forceinline__ float bfh(float v) {
    return __bfloat162float(__float2bfloat16_rn(v));
}

#define CPA(dst, src) \
    asm volatile("cp.async.cg.shared.global [%0], [%1], 16;" :: "r"(dst), "l"(src))
#define CP_COMMIT() asm volatile("cp.async.commit_group;" ::: "memory")
#define CP_WAIT1()  asm volatile("cp.async.wait_group 1;" ::: "memory")

#define LDSM4(r0, r1, r2, r3, addr) \
    asm volatile("ldmatrix.sync.aligned.m8n8.x4.shared.b16 {%0,%1,%2,%3}, [%4];" \
                 : "=r"(r0), "=r"(r1), "=r"(r2), "=r"(r3) : "r"(addr))

#define MMA16816(d, a, b0, b1) \
    asm volatile("mma.sync.aligned.m16n8k16.row.col.f32.bf16.bf16.f32 " \
                 "{%0,%1,%2,%3}, {%4,%5,%6,%7}, {%8,%9}, {%0,%1,%2,%3};" \
                 : "+f"(d[0]), "+f"(d[1]), "+f"(d[2]), "+f"(d[3]) \
                 : "r"(a[0]), "r"(a[1]), "r"(a[2]), "r"(a[3]), "r"(b0), "r"(b1))

// ---------------- prep: fp32 -> bf16 hi/lo planes ----------------
__global__ __launch_bounds__(256, 4)
void prep_kernel(const float* __restrict__ x, const float* __restrict__ W) {
    int idx = blockIdx.x * 256 + threadIdx.x;   // < 512*320
    int r = idx / 320;
    int d0 = (idx - r * 320) * 4;
    size_t p = (size_t)r * DDIM + d0;

    float4 xv = *(const float4*)&x[p];
    float4 wA = *(const float4*)&W[2 * d0];      // (w0,w1) for d0, d0+1
    float4 wB = *(const float4*)&W[2 * d0 + 4];  // d0+2, d0+3

    float h0 = bfh(xv.x), h1 = bfh(xv.y), h2 = bfh(xv.z), h3 = bfh(xv.w);
    *(uint2*)&g_Xhi[p] = make_uint2(pkbf2(h0, h1), pkbf2(h2, h3));
    *(uint2*)&g_Xlo[p] = make_uint2(pkbf2(xv.x - h0, xv.y - h1), pkbf2(xv.z - h2, xv.w - h3));

    float z0 = xv.x * wA.x, z1 = xv.y * wA.z, z2 = xv.z * wB.x, z3 = xv.w * wB.z;
    h0 = bfh(z0); h1 = bfh(z1); h2 = bfh(z2); h3 = bfh(z3);
    *(uint2*)&g_Zhi[0][p] = make_uint2(pkbf2(h0, h1), pkbf2(h2, h3));
    *(uint2*)&g_Zlo[0][p] = make_uint2(pkbf2(z0 - h0, z1 - h1), pkbf2(z2 - h2, z3 - h3));

    z0 = xv.x * wA.y; z1 = xv.y * wA.w; z2 = xv.z * wB.y; z3 = xv.w * wB.w;
    h0 = bfh(z0); h1 = bfh(z1); h2 = bfh(z2); h3 = bfh(z3);
    *(uint2*)&g_Zhi[1][p] = make_uint2(pkbf2(h0, h1), pkbf2(h2, h3));
    *(uint2*)&g_Zlo[1][p] = make_uint2(pkbf2(z0 - h0, z1 - h1), pkbf2(z2 - h2, z3 - h3));
}

// ---------------- GEMM: D[64(mk),32(n)] = Z Xs^T per tile ----------------
__global__ __launch_bounds__(256, 1)
void pcm_mma_kernel(float* __restrict__ out, const float* __restrict__ bias) {
    extern __shared__ char smraw[];
    uint32_t sb = smem_u32(smraw);
    uint32_t base = (sb + 127) & ~127u;
    char* smc = smraw + (base - sb);

    // triangular tile decode
    int t = blockIdx.x, ti = 0;
    while (t >= NTB - ti) { t -= NTB - ti; ++ti; }
    int tj = ti + t;
    const int i0 = ti * 32, j0 = tj * 32;

    const int tid = threadIdx.x;
    const int wid = tid >> 5, L = tid & 31;

    // ---- copy lanes: row = tid>>3 (0..31), 16B col group = tid&7
    const int arow = tid >> 3;
    const int cg = tid & 7;
    int ri = i0 + arow + 1; if (ri > 511) ri = 511;
    int rj = j0 + arow + 1; if (rj > 511) rj = 511;
    const __nv_bfloat16* sAh0 = &g_Zhi[0][(size_t)ri * DDIM + cg * 8];
    const __nv_bfloat16* sAh1 = &g_Zhi[1][(size_t)ri * DDIM + cg * 8];
    const __nv_bfloat16* sAl0 = &g_Zlo[0][(size_t)ri * DDIM + cg * 8];
    const __nv_bfloat16* sAl1 = &g_Zlo[1][(size_t)ri * DDIM + cg * 8];
    const __nv_bfloat16* sBh  = &g_Xhi[(size_t)rj * DDIM + cg * 8];
    const __nv_bfloat16* sBl  = &g_Xlo[(size_t)rj * DDIM + cg * 8];
    const uint32_t swc = (uint32_t)((cg * 16) ^ ((arow & 7) * 16));
    const uint32_t dA0  = SA_HI + arow * 128 + swc;
    const uint32_t dA1  = SA_HI + (arow + 32) * 128 + swc;
    const uint32_t dAl0 = SA_LO + arow * 128 + swc;
    const uint32_t dAl1 = SA_LO + (arow + 32) * 128 + swc;
    const uint32_t dB   = SB_HI + arow * 128 + swc;
    const uint32_t dBl  = SB_LO + arow * 128 + swc;

    // prologue: chunks 0..STAGES-2
#pragma unroll
    for (int c = 0; c < STAGES - 1; c++) {
        uint32_t st = base + c * STAGE_BYTES;
        size_t off = (size_t)c * KC;
        CPA(st + dA0, sAh0 + off);  CPA(st + dA1, sAh1 + off);
        CPA(st + dAl0, sAl0 + off); CPA(st + dAl1, sAl1 + off);
        CPA(st + dB, sBh + off);    CPA(st + dBl, sBl + off);
        CP_COMMIT();
    }

    // ---- mma fragment addressing (per lane, swizzle-resolved)
    const int warpM = wid >> 1;        // 0..3 -> A rows 16*warpM
    const int warpN = wid & 1;         // 0..1 -> B rows 16*warpN
    const int a_r = warpM * 16 + (L & 7) + ((L >> 3) & 1) * 8;   // 0..63
    const uint32_t a_cb0 = ((L >> 4) & 1) * 16;
    const uint32_t a_xm = (a_r & 7) * 16;
    const uint32_t aRow = SA_HI + a_r * 128;
    const int b_r = warpN * 16 + (L & 7) + ((L >> 4) & 1) * 8;   // 0..31
    const uint32_t b_cb0 = ((L >> 3) & 1) * 16;
    const uint32_t b_xm = (b_r & 7) * 16;
    const uint32_t bRow = SB_HI + b_r * 128;

    float acc0[4] = {0.f, 0.f, 0.f, 0.f};
    float acc1[4] = {0.f, 0.f, 0.f, 0.f};

    for (int c = 0; c < NCH; c++) {
        CP_WAIT1();
        __syncthreads();      // chunk c resident; all warps done with chunk c-1's smem

        if (c + STAGES - 1 < NCH) {
            uint32_t st = base + ((c + STAGES - 1) % STAGES) * STAGE_BYTES;
            size_t off = (size_t)(c + STAGES - 1) * KC;
            CPA(st + dA0, sAh0 + off);  CPA(st + dA1, sAh1 + off);
            CPA(st + dAl0, sAl0 + off); CPA(st + dAl1, sAl1 + off);
            CPA(st + dB, sBh + off);    CPA(st + dBl, sBl + off);
        }
        CP_COMMIT();

        const uint32_t stg = base + (c % STAGES) * STAGE_BYTES;
#pragma unroll
        for (int kk = 0; kk < 4; kk++) {
            uint32_t ah[4], al[4], bh[4], bl[4];
            const uint32_t aAddr = stg + aRow + ((a_cb0 + kk * 32) ^ a_xm);
            const uint32_t bAddr = stg + bRow + ((b_cb0 + kk * 32) ^ b_xm);
            LDSM4(ah[0], ah[1], ah[2], ah[3], aAddr);
            LDSM4(al[0], al[1], al[2], al[3], aAddr + (SA_LO - SA_HI));
            LDSM4(bh[0], bh[1], bh[2], bh[3], bAddr);
            LDSM4(bl[0], bl[1], bl[2], bl[3], bAddr + (SB_LO - SB_HI));
            MMA16816(acc0, ah, bh[0], bh[1]);  MMA16816(acc1, ah, bh[2], bh[3]);
            MMA16816(acc0, ah, bl[0], bl[1]);  MMA16816(acc1, ah, bl[2], bl[3]);
            MMA16816(acc0, al, bh[0], bh[1]);  MMA16816(acc1, al, bh[2], bh[3]);
        }
    }

    // ---- stage D (64x32, rows 0-31 = k0, 32-63 = k1) in smem, stride 33
    float* Ds = (float*)smc;
    {
        const int dr = warpM * 16 + (L >> 2);
        const int dc = warpN * 16 + (L & 3) * 2;
        Ds[dr * 33 + dc]           = acc0[0];
        Ds[dr * 33 + dc + 1]       = acc0[1];
        Ds[(dr + 8) * 33 + dc]     = acc0[2];
        Ds[(dr + 8) * 33 + dc + 1] = acc0[3];
        Ds[dr * 33 + dc + 8]       = acc1[0];
        Ds[dr * 33 + dc + 9]       = acc1[1];
        Ds[(dr + 8) * 33 + dc + 8] = acc1[2];
        Ds[(dr + 8) * 33 + dc + 9] = acc1[3];
    }
    __syncthreads();

    const float b0 = bias[0], b1 = bias[1];

    // main orientation: out[i][j][k], float4 = (j,k0),(j,k1),(j+1,k0),(j+1,k1)
#pragma unroll
    for (int p = 0; p < 2; p++) {
        int task = tid + p * 256;
        int r = task & 31, cp = task >> 5;     // r: i-row, cp: j-pair
        int i = i0 + r, j = j0 + 2 * cp;
        if (i < OUTN && j < OUTN - 1) {
            float4 v = make_float4(Ds[r * 33 + 2 * cp] + b0,
                                   Ds[(r + 32) * 33 + 2 * cp] + b1,
                                   Ds[r * 33 + 2 * cp + 1] + b0,
                                   Ds[(r + 32) * 33 + 2 * cp + 1] + b1);
            *(float4*)&out[((size_t)i * OUTN + j) * 2] = v;
        }
    }

    // mirror orientation: out[j][i][k] (skip on diagonal tiles)
    if (ti != tj) {
#pragma unroll
        for (int p = 0; p < 2; p++) {
            int task = tid + p * 256;
            int cc = task & 31, rp = task >> 5; // cc: j-row, rp: i-pair
            int jj = j0 + cc, i = i0 + 2 * rp;
            if (jj < OUTN) {
                float4 v = make_float4(Ds[(2 * rp) * 33 + cc] + b0,
                                       Ds[(2 * rp + 32) * 33 + cc] + b1,
                                       Ds[(2 * rp + 1) * 33 + cc] + b0,
                                       Ds[(2 * rp + 33) * 33 + cc] + b1);
                *(float4*)&out[((size_t)jj * OUTN + i) * 2] = v;
            }
        }
    }
}

extern "C" void kernel_launch(void* const* d_in, const int* in_sizes, int n_in,
                              void* d_out, int out_size) {
    const float* x = (const float*)d_in[0];   // (1,512,1280) fp32
    const float* W = (const float*)d_in[1];   // (2560,2) fp32
    const float* b = (const float*)d_in[2];   // (2,) fp32
    float* out = (float*)d_out;               // (1,510,510,2) fp32

    prep_kernel<<<640, 256>>>(x, W);

    static int attr_set = 0;
    cudaFuncSetAttribute(pcm_mma_kernel,
                         cudaFuncAttributeMaxDynamicSharedMemorySize, SMEM_REQ);
    (void)attr_set;

    pcm_mma_kernel<<<NTRI, 256, SMEM_REQ>>>(out, b);
}

// round 5
// speedup vs baseline: 2.5227x; 1.2937x over previous
#include <cuda_runtime.h>
#include <cuda_fp16.h>
#include <cstdint>

// out[i,j,k] = sum_d x[i+1,d]*x[j+1,d]*Wp[d,k] + b[k]
// (diff_term antisymmetric -> cancels under (i,j) symmetrization; prod_term symmetric)
//
// Asymmetric fp16 split on legacy mma.sync (family-portable):
//   A = Z = x*wp : Zh (fp16) + Zl (fp16, residual * 4096)  -> A error ~2^-22
//   B = X        : single fp16                             -> output err ~2.8e-4 << 1e-3
// acc = accH + accL/4096. 136 triangular 32x32 tiles, K=1280, 3-stage cp.async.

#define OUTN 510
#define DDIM 1280
#define NTB 16
#define NTRI 136
#define KC 64
#define NCH 20
#define STAGES 3
#define STAGE_BYTES 20480   // Ahi 8K | Alo 8K | Bhi 4K
#define SA_HI 0
#define SA_LO 8192
#define SB_HI 16384
#define SMEM_REQ (STAGES * STAGE_BYTES + 128)

__device__ __align__(128) __half g_Xh[512 * DDIM];
__device__ __align__(128) __half g_Zh[2][512 * DDIM];
__device__ __align__(128) __half g_Zl[2][512 * DDIM];

// ---------------- helpers ----------------
__device__ __forceinline__ uint32_t smem_u32(const void* p) {
    uint32_t a;
    asm("{ .reg .u64 t; cvta.to.shared.u64 t, %1; cvt.u32.u64 %0, t; }" : "=r"(a) : "l"(p));
    return a;
}
__device__ __forceinline__ uint32_t pk2h(float a, float b) {
    __half2 t = __floats2half2_rn(a, b);
    return *reinterpret_cast<uint32_t*>(&t);
}
__device__ __forceinline__ float h16(float v) {
    return __half2float(__float2half_rn(v));
}

#define CPA(dst, src) \
    asm volatile("cp.async.cg.shared.global [%0], [%1], 16;" :: "r"(dst), "l"(src))
#define CP_COMMIT() asm volatile("cp.async.commit_group;" ::: "memory")
#define CP_WAIT1()  asm volatile("cp.async.wait_group 1;" ::: "memory")

#define LDSM4(r0, r1, r2, r3, addr) \
    asm volatile("ldmatrix.sync.aligned.m8n8.x4.shared.b16 {%0,%1,%2,%3}, [%4];" \
                 : "=r"(r0), "=r"(r1), "=r"(r2), "=r"(r3) : "r"(addr))

#define MMA16816(d, a, b0, b1) \
    asm volatile("mma.sync.aligned.m16n8k16.row.col.f32.f16.f16.f32 " \
                 "{%0,%1,%2,%3}, {%4,%5,%6,%7}, {%8,%9}, {%0,%1,%2,%3};" \
                 : "+f"(d[0]), "+f"(d[1]), "+f"(d[2]), "+f"(d[3]) \
                 : "r"(a[0]), "r"(a[1]), "r"(a[2]), "r"(a[3]), "r"(b0), "r"(b1))

// ---------------- prep: fp32 -> fp16 planes ----------------
__global__ __launch_bounds__(256, 4)
void prep_kernel(const float* __restrict__ x, const float* __restrict__ W) {
    int idx = blockIdx.x * 256 + threadIdx.x;   // < 512*320
    int r = idx / 320;
    int d0 = (idx - r * 320) * 4;
    size_t p = (size_t)r * DDIM + d0;

    float4 xv = *(const float4*)&x[p];
    float4 wA = *(const float4*)&W[2 * d0];      // (w0,w1) for d0, d0+1
    float4 wB = *(const float4*)&W[2 * d0 + 4];  // d0+2, d0+3

    *(uint2*)&g_Xh[p] = make_uint2(pk2h(xv.x, xv.y), pk2h(xv.z, xv.w));

    float z0 = xv.x * wA.x, z1 = xv.y * wA.z, z2 = xv.z * wB.x, z3 = xv.w * wB.z;
    float h0 = h16(z0), h1 = h16(z1), h2 = h16(z2), h3 = h16(z3);
    *(uint2*)&g_Zh[0][p] = make_uint2(pk2h(z0, z1), pk2h(z2, z3));
    *(uint2*)&g_Zl[0][p] = make_uint2(pk2h((z0 - h0) * 4096.f, (z1 - h1) * 4096.f),
                                      pk2h((z2 - h2) * 4096.f, (z3 - h3) * 4096.f));

    z0 = xv.x * wA.y; z1 = xv.y * wA.w; z2 = xv.z * wB.y; z3 = xv.w * wB.w;
    h0 = h16(z0); h1 = h16(z1); h2 = h16(z2); h3 = h16(z3);
    *(uint2*)&g_Zh[1][p] = make_uint2(pk2h(z0, z1), pk2h(z2, z3));
    *(uint2*)&g_Zl[1][p] = make_uint2(pk2h((z0 - h0) * 4096.f, (z1 - h1) * 4096.f),
                                      pk2h((z2 - h2) * 4096.f, (z3 - h3) * 4096.f));
}

// ---------------- GEMM: D[64(mk),32(n)] = Z Xs^T per tile ----------------
__global__ __launch_bounds__(256, 1)
void pcm_mma_kernel(float* __restrict__ out, const float* __restrict__ bias) {
    extern __shared__ char smraw[];
    uint32_t sb = smem_u32(smraw);
    uint32_t base = (sb + 127) & ~127u;
    char* smc = smraw + (base - sb);

    // triangular tile decode
    int t = blockIdx.x, ti = 0;
    while (t >= NTB - ti) { t -= NTB - ti; ++ti; }
    int tj = ti + t;
    const int i0 = ti * 32, j0 = tj * 32;

    const int tid = threadIdx.x;
    const int wid = tid >> 5, L = tid & 31;

    // ---- copy lanes: row = tid>>3 (0..31), 16B col group = tid&7
    const int arow = tid >> 3;
    const int cg = tid & 7;
    int ri = i0 + arow + 1; if (ri > 511) ri = 511;
    int rj = j0 + arow + 1; if (rj > 511) rj = 511;
    const __half* sAh0 = &g_Zh[0][(size_t)ri * DDIM + cg * 8];
    const __half* sAh1 = &g_Zh[1][(size_t)ri * DDIM + cg * 8];
    const __half* sAl0 = &g_Zl[0][(size_t)ri * DDIM + cg * 8];
    const __half* sAl1 = &g_Zl[1][(size_t)ri * DDIM + cg * 8];
    const __half* sBh  = &g_Xh[(size_t)rj * DDIM + cg * 8];
    const uint32_t swc = (uint32_t)((cg * 16) ^ ((arow & 7) * 16));
    const uint32_t dA0  = SA_HI + arow * 128 + swc;
    const uint32_t dA1  = SA_HI + (arow + 32) * 128 + swc;
    const uint32_t dAl0 = SA_LO + arow * 128 + swc;
    const uint32_t dAl1 = SA_LO + (arow + 32) * 128 + swc;
    const uint32_t dB   = SB_HI + arow * 128 + swc;

    // prologue: chunks 0..STAGES-2
#pragma unroll
    for (int c = 0; c < STAGES - 1; c++) {
        uint32_t st = base + c * STAGE_BYTES;
        size_t off = (size_t)c * KC;
        CPA(st + dA0, sAh0 + off);  CPA(st + dA1, sAh1 + off);
        CPA(st + dAl0, sAl0 + off); CPA(st + dAl1, sAl1 + off);
        CPA(st + dB, sBh + off);
        CP_COMMIT();
    }

    // ---- mma fragment addressing (per lane, swizzle-resolved)
    const int warpM = wid >> 1;        // 0..3 -> A rows 16*warpM
    const int warpN = wid & 1;         // 0..1 -> B rows 16*warpN
    const int a_r = warpM * 16 + (L & 7) + ((L >> 3) & 1) * 8;   // 0..63
    const uint32_t a_cb0 = ((L >> 4) & 1) * 16;
    const uint32_t a_xm = (a_r & 7) * 16;
    const uint32_t aRow = SA_HI + a_r * 128;
    const int b_r = warpN * 16 + (L & 7) + ((L >> 4) & 1) * 8;   // 0..31
    const uint32_t b_cb0 = ((L >> 3) & 1) * 16;
    const uint32_t b_xm = (b_r & 7) * 16;
    const uint32_t bRow = SB_HI + b_r * 128;

    float acc0H[4] = {0.f, 0.f, 0.f, 0.f};
    float acc1H[4] = {0.f, 0.f, 0.f, 0.f};
    float acc0L[4] = {0.f, 0.f, 0.f, 0.f};
    float acc1L[4] = {0.f, 0.f, 0.f, 0.f};

    for (int c = 0; c < NCH; c++) {
        CP_WAIT1();
        __syncthreads();      // chunk c resident; all warps done with chunk c-1's smem

        if (c + STAGES - 1 < NCH) {
            uint32_t st = base + ((c + STAGES - 1) % STAGES) * STAGE_BYTES;
            size_t off = (size_t)(c + STAGES - 1) * KC;
            CPA(st + dA0, sAh0 + off);  CPA(st + dA1, sAh1 + off);
            CPA(st + dAl0, sAl0 + off); CPA(st + dAl1, sAl1 + off);
            CPA(st + dB, sBh + off);
        }
        CP_COMMIT();

        const uint32_t stg = base + (c % STAGES) * STAGE_BYTES;
#pragma unroll
        for (int kk = 0; kk < 4; kk++) {
            uint32_t ah[4], al[4], bh[4];
            const uint32_t aAddr = stg + aRow + ((a_cb0 + kk * 32) ^ a_xm);
            const uint32_t bAddr = stg + bRow + ((b_cb0 + kk * 32) ^ b_xm);
            LDSM4(ah[0], ah[1], ah[2], ah[3], aAddr);
            LDSM4(al[0], al[1], al[2], al[3], aAddr + (SA_LO - SA_HI));
            LDSM4(bh[0], bh[1], bh[2], bh[3], bAddr);
            MMA16816(acc0H, ah, bh[0], bh[1]);  MMA16816(acc1H, ah, bh[2], bh[3]);
            MMA16816(acc0L, al, bh[0], bh[1]);  MMA16816(acc1L, al, bh[2], bh[3]);
        }
    }

    // ---- stage D (64x32, rows 0-31 = k0, 32-63 = k1) in smem, stride 33
    float* Ds = (float*)smc;
    {
        const float s = 1.f / 4096.f;
        const int dr = warpM * 16 + (L >> 2);
        const int dc = warpN * 16 + (L & 3) * 2;
        Ds[dr * 33 + dc]           = acc0H[0] + s * acc0L[0];
        Ds[dr * 33 + dc + 1]       = acc0H[1] + s * acc0L[1];
        Ds[(dr + 8) * 33 + dc]     = acc0H[2] + s * acc0L[2];
        Ds[(dr + 8) * 33 + dc + 1] = acc0H[3] + s * acc0L[3];
        Ds[dr * 33 + dc + 8]       = acc1H[0] + s * acc1L[0];
        Ds[dr * 33 + dc + 9]       = acc1H[1] + s * acc1L[1];
        Ds[(dr + 8) * 33 + dc + 8] = acc1H[2] + s * acc1L[2];
        Ds[(dr + 8) * 33 + dc + 9] = acc1H[3] + s * acc1L[3];
    }
    __syncthreads();

    const float b0 = bias[0], b1 = bias[1];

    // main orientation: out[i][j][k], float4 = (j,k0),(j,k1),(j+1,k0),(j+1,k1)
#pragma unroll
    for (int p = 0; p < 2; p++) {
        int task = tid + p * 256;
        int r = task & 31, cp = task >> 5;     // r: i-row, cp: j-pair
        int i = i0 + r, j = j0 + 2 * cp;
        if (i < OUTN && j < OUTN - 1) {
            float4 v = make_float4(Ds[r * 33 + 2 * cp] + b0,
                                   Ds[(r + 32) * 33 + 2 * cp] + b1,
                                   Ds[r * 33 + 2 * cp + 1] + b0,
                                   Ds[(r + 32) * 33 + 2 * cp + 1] + b1);
            *(float4*)&out[((size_t)i * OUTN + j) * 2] = v;
        }
    }

    // mirror orientation: out[j][i][k] (skip on diagonal tiles)
    if (ti != tj) {
#pragma unroll
        for (int p = 0; p < 2; p++) {
            int task = tid + p * 256;
            int cc = task & 31, rp = task >> 5; // cc: j-row, rp: i-pair
            int jj = j0 + cc, i = i0 + 2 * rp;
            if (jj < OUTN) {
                float4 v = make_float4(Ds[(2 * rp) * 33 + cc] + b0,
                                       Ds[(2 * rp + 32) * 33 + cc] + b1,
                                       Ds[(2 * rp + 1) * 33 + cc] + b0,
                                       Ds[(2 * rp + 33) * 33 + cc] + b1);
                *(float4*)&out[((size_t)jj * OUTN + i) * 2] = v;
            }
        }
    }
}

extern "C" void kernel_launch(void* const* d_in, const int* in_sizes, int n_in,
                              void* d_out, int out_size) {
    const float* x = (const float*)d_in[0];   // (1,512,1280) fp32
    const float* W = (const float*)d_in[1];   // (2560,2) fp32
    const float* b = (const float*)d_in[2];   // (2,) fp32
    float* out = (float*)d_out;               // (1,510,510,2) fp32

    prep_kernel<<<640, 256>>>(x, W);

    cudaFuncSetAttribute(pcm_mma_kernel,
                         cudaFuncAttributeMaxDynamicSharedMemorySize, SMEM_REQ);

    pcm_mma_kernel<<<NTRI, 256, SMEM_REQ>>>(out, b);
}